// round 2
// baseline (speedup 1.0000x reference)
#include <cuda_runtime.h>

// Problem constants (B=64, S=1024, D=768, R=4)
#define DD   768
#define ND   2304           // 3*D
#define RR   4
#define MTOT 65536          // B*S

// GEMM tiling
#define BM 128
#define BN 128
#define BKT 16
#define TM 8
#define TN 8

// Scratch for the folded weight (LoRA delta absorbed into W): 2304x768 f32 = 7 MB
__device__ float g_Weff[ND * DD];

// ---------------------------------------------------------------------------
// Kernel 1: W_eff[e][d] = W_qkv[e][d] + s0 * (rank-4 LoRA delta on q/v rows)
// ---------------------------------------------------------------------------
__global__ void build_weff(const float* __restrict__ W,
                           const float* __restrict__ Aq,   // [R, D]
                           const float* __restrict__ Bq,   // [D, R]
                           const float* __restrict__ Av,   // [R, D]
                           const float* __restrict__ Bv,   // [D, R]
                           const float* __restrict__ s0p) {
    int idx = blockIdx.x * blockDim.x + threadIdx.x;
    if (idx >= ND * DD) return;
    int e = idx / DD;
    int d = idx - e * DD;
    float v = W[idx];
    float s = s0p[0];
    if (e < DD) {
        float acc = 0.f;
#pragma unroll
        for (int r = 0; r < RR; r++)
            acc = fmaf(Bq[e * RR + r], Aq[r * DD + d], acc);
        v = fmaf(s, acc, v);
    } else if (e >= 2 * DD) {
        int e2 = e - 2 * DD;
        float acc = 0.f;
#pragma unroll
        for (int r = 0; r < RR; r++)
            acc = fmaf(Bv[e2 * RR + r], Av[r * DD + d], acc);
        v = fmaf(s, acc, v);
    }
    g_Weff[idx] = v;
}

// ---------------------------------------------------------------------------
// Kernel 2: Out[M, ND] = X[M, D] @ W_eff[ND, D]^T + bias[ND]
// Classic smem-tiled SGEMM: 128x128 block tile, BK=16, 8x8 per thread.
// All dims divide the tile sizes exactly (65536/128, 2304/128, 768/16).
// ---------------------------------------------------------------------------
__global__ __launch_bounds__(256, 2)
void sgemm_bias(const float* __restrict__ X,
                const float* __restrict__ bias,
                float* __restrict__ Out) {
    __shared__ float As[BKT][BM];
    __shared__ float Bs[BKT][BN];

    const int n0 = blockIdx.x * BN;
    const int m0 = blockIdx.y * BM;
    const int t  = threadIdx.x;          // 0..255
    const int tx = t & 15;               // column thread  (TN cols each)
    const int ty = t >> 4;               // row thread     (TM rows each)

    // Global-load mapping: the 128x16 tile = 512 float4; 2 per thread.
    const int lrow  = t >> 2;            // 0..63 (plus +64 for second half)
    const int lcol4 = t & 3;             // which float4 within the 16-wide row
    const int kbase = lcol4 * 4;

    const float* Aptr = X      + (size_t)m0 * DD;
    const float* Bptr = g_Weff + (size_t)n0 * DD;

    float acc[TM][TN];
#pragma unroll
    for (int i = 0; i < TM; i++)
#pragma unroll
        for (int j = 0; j < TN; j++) acc[i][j] = 0.f;

    for (int k0 = 0; k0 < DD; k0 += BKT) {
#pragma unroll
        for (int h = 0; h < 2; h++) {
            const int row = lrow + h * 64;
            float4 va = *reinterpret_cast<const float4*>(
                Aptr + (size_t)row * DD + k0 + kbase);
            As[kbase + 0][row] = va.x;
            As[kbase + 1][row] = va.y;
            As[kbase + 2][row] = va.z;
            As[kbase + 3][row] = va.w;
            float4 vb = *reinterpret_cast<const float4*>(
                Bptr + (size_t)row * DD + k0 + kbase);
            Bs[kbase + 0][row] = vb.x;
            Bs[kbase + 1][row] = vb.y;
            Bs[kbase + 2][row] = vb.z;
            Bs[kbase + 3][row] = vb.w;
        }
        __syncthreads();

#pragma unroll
        for (int k = 0; k < BKT; k++) {
            float a[TM], b[TN];
            *reinterpret_cast<float4*>(&a[0]) =
                *reinterpret_cast<const float4*>(&As[k][ty * TM]);
            *reinterpret_cast<float4*>(&a[4]) =
                *reinterpret_cast<const float4*>(&As[k][ty * TM + 4]);
            *reinterpret_cast<float4*>(&b[0]) =
                *reinterpret_cast<const float4*>(&Bs[k][tx * TN]);
            *reinterpret_cast<float4*>(&b[4]) =
                *reinterpret_cast<const float4*>(&Bs[k][tx * TN + 4]);
#pragma unroll
            for (int i = 0; i < TM; i++)
#pragma unroll
                for (int j = 0; j < TN; j++)
                    acc[i][j] = fmaf(a[i], b[j], acc[i][j]);
        }
        __syncthreads();
    }

    // Epilogue: add bias, vectorized stores.
    float bb[TN];
#pragma unroll
    for (int j = 0; j < TN; j++) bb[j] = bias[n0 + tx * TN + j];

#pragma unroll
    for (int i = 0; i < TM; i++) {
        const size_t row = (size_t)(m0 + ty * TM + i);
        float4 o0, o1;
        o0.x = acc[i][0] + bb[0];
        o0.y = acc[i][1] + bb[1];
        o0.z = acc[i][2] + bb[2];
        o0.w = acc[i][3] + bb[3];
        o1.x = acc[i][4] + bb[4];
        o1.y = acc[i][5] + bb[5];
        o1.z = acc[i][6] + bb[6];
        o1.w = acc[i][7] + bb[7];
        float* orow = Out + row * ND + n0 + tx * TN;
        *reinterpret_cast<float4*>(orow)     = o0;
        *reinterpret_cast<float4*>(orow + 4) = o1;
    }
}

// ---------------------------------------------------------------------------
// Launch
// Inputs (metadata order): x, W_qkv, b_qkv, A_q, B_q, A_v, B_v, s0
// ---------------------------------------------------------------------------
extern "C" void kernel_launch(void* const* d_in, const int* in_sizes, int n_in,
                              void* d_out, int out_size) {
    const float* x  = (const float*)d_in[0];
    const float* W  = (const float*)d_in[1];
    const float* b  = (const float*)d_in[2];
    const float* Aq = (const float*)d_in[3];
    const float* Bq = (const float*)d_in[4];
    const float* Av = (const float*)d_in[5];
    const float* Bv = (const float*)d_in[6];
    const float* s0 = (const float*)d_in[7];
    float* out = (float*)d_out;

    build_weff<<<(ND * DD + 255) / 256, 256>>>(W, Aq, Bq, Av, Bv, s0);

    dim3 grid(ND / BN, MTOT / BM);   // (18, 512)
    sgemm_bias<<<grid, 256>>>(x, b, out);
}

// round 4
// speedup vs baseline: 1.9302x; 1.9302x over previous
#include <cuda_runtime.h>
#include <cuda_bf16.h>
#include <cstdint>

// Problem constants (B=64, S=1024, D=768, R=4)
#define DD    768
#define ND    2304
#define RR    4
#define MTOT  65536

// GEMM tiling
#define BM 128
#define BN 128
#define BK 32
#define NKT (DD / BK)        // 24
#define STAGES 3

// smem stage layout: padded rows of 40 bf16 (80 B) for conflict-free ldmatrix
#define ROWB   80
#define MAT_B  (128 * ROWB)  // 10240 bytes per matrix tile
#define A_HI   0
#define A_LO   (MAT_B)
#define B_HI   (2 * MAT_B)
#define B_LO   (3 * MAT_B)
#define STG    (4 * MAT_B)   // 40960
#define SMEM_TOTAL (STAGES * STG)  // 122880

// Static device scratch (no runtime allocation allowed)
__device__ __align__(128) __nv_bfloat16 g_Xhi[(size_t)MTOT * DD];
__device__ __align__(128) __nv_bfloat16 g_Xlo[(size_t)MTOT * DD];
__device__ __align__(128) __nv_bfloat16 g_Whi[(size_t)ND * DD];
__device__ __align__(128) __nv_bfloat16 g_Wlo[(size_t)ND * DD];

// ---------------------------------------------------------------------------
// PTX helpers (all baseline ISA: sm_80/75 — safe for compute_103 virtual arch)
// ---------------------------------------------------------------------------
__device__ __forceinline__ uint32_t smem_u32(const void* p) {
    uint32_t a;
    asm("{ .reg .u64 t; cvta.to.shared.u64 t, %1; cvt.u32.u64 %0, t; }"
        : "=r"(a) : "l"(p));
    return a;
}

#define CPA(saddr, gaddr) \
    asm volatile("cp.async.cg.shared.global [%0], [%1], 16;" \
                 :: "r"(saddr), "l"(gaddr))

#define CP_COMMIT() asm volatile("cp.async.commit_group;" ::: "memory")
#define CP_WAIT1()  asm volatile("cp.async.wait_group 1;" ::: "memory")

#define LDSM4(r, addr)                                                        \
    asm volatile("ldmatrix.sync.aligned.m8n8.x4.shared.b16 {%0,%1,%2,%3}, [%4];" \
                 : "=r"((r)[0]), "=r"((r)[1]), "=r"((r)[2]), "=r"((r)[3])     \
                 : "r"(addr))

#define MMA(c, a, b0, b1)                                                     \
    asm volatile("mma.sync.aligned.m16n8k16.row.col.f32.bf16.bf16.f32 "       \
                 "{%0,%1,%2,%3},{%4,%5,%6,%7},{%8,%9},{%0,%1,%2,%3};"         \
                 : "+f"((c)[0]), "+f"((c)[1]), "+f"((c)[2]), "+f"((c)[3])     \
                 : "r"((a)[0]), "r"((a)[1]), "r"((a)[2]), "r"((a)[3]),        \
                   "r"(b0), "r"(b1))

// ---------------------------------------------------------------------------
// Kernel 0: X fp32 -> (X_hi, X_lo) bf16 split
// ---------------------------------------------------------------------------
__global__ void conv_x(const float4* __restrict__ X) {
    size_t i = (size_t)blockIdx.x * blockDim.x + threadIdx.x;   // float4 index
    float4 v = X[i];
    __nv_bfloat16 h0 = __float2bfloat16(v.x), h1 = __float2bfloat16(v.y);
    __nv_bfloat16 h2 = __float2bfloat16(v.z), h3 = __float2bfloat16(v.w);
    __nv_bfloat16 l0 = __float2bfloat16(v.x - __bfloat162float(h0));
    __nv_bfloat16 l1 = __float2bfloat16(v.y - __bfloat162float(h1));
    __nv_bfloat16 l2 = __float2bfloat16(v.z - __bfloat162float(h2));
    __nv_bfloat16 l3 = __float2bfloat16(v.w - __bfloat162float(h3));
    __nv_bfloat162* ph = reinterpret_cast<__nv_bfloat162*>(g_Xhi) + i * 2;
    __nv_bfloat162* pl = reinterpret_cast<__nv_bfloat162*>(g_Xlo) + i * 2;
    ph[0] = __nv_bfloat162(h0, h1);
    ph[1] = __nv_bfloat162(h2, h3);
    pl[0] = __nv_bfloat162(l0, l1);
    pl[1] = __nv_bfloat162(l2, l3);
}

// ---------------------------------------------------------------------------
// Kernel 1: fold LoRA into W (rank-4 update on q and v row blocks), split
// ---------------------------------------------------------------------------
__global__ void fold_w(const float* __restrict__ W,
                       const float* __restrict__ Aq, const float* __restrict__ Bq,
                       const float* __restrict__ Av, const float* __restrict__ Bv,
                       const float* __restrict__ s0p) {
    int idx = blockIdx.x * blockDim.x + threadIdx.x;
    if (idx >= ND * DD) return;
    int e = idx / DD;
    int d = idx - e * DD;
    float v = W[idx];
    float s = s0p[0];
    if (e < DD) {
        float acc = 0.f;
#pragma unroll
        for (int r = 0; r < RR; r++) acc = fmaf(Bq[e * RR + r], Aq[r * DD + d], acc);
        v = fmaf(s, acc, v);
    } else if (e >= 2 * DD) {
        int e2 = e - 2 * DD;
        float acc = 0.f;
#pragma unroll
        for (int r = 0; r < RR; r++) acc = fmaf(Bv[e2 * RR + r], Av[r * DD + d], acc);
        v = fmaf(s, acc, v);
    }
    __nv_bfloat16 hi = __float2bfloat16(v);
    __nv_bfloat16 lo = __float2bfloat16(v - __bfloat162float(hi));
    g_Whi[idx] = hi;
    g_Wlo[idx] = lo;
}

// ---------------------------------------------------------------------------
// Kernel 2: bf16 mma.sync GEMM with 3-term split, fp32 accumulate.
//   Out[M, ND] = Xs @ Ws^T + bias
//   128x128x32 CTA tile, 8 warps (2x4), 64x32 warp tile, 3-stage cp.async.
// ---------------------------------------------------------------------------
__global__ void __launch_bounds__(256, 1) gemm_mma(
    const float* __restrict__ bias, float* __restrict__ Out) {
    extern __shared__ char smem[];
    const uint32_t sb = smem_u32(smem);

    const int tid  = threadIdx.x;
    const int wid  = tid >> 5;
    const int lane = tid & 31;
    const int wm   = wid >> 2;          // 0..1  (64 rows each)
    const int wn   = wid & 3;           // 0..3  (32 cols each)
    const int n0   = blockIdx.x * BN;
    const int m0   = blockIdx.y * BM;

    // global load mapping: 512 16B chunks per matrix tile, 2 per thread
    const int r0c = tid >> 2;           // row for chunk 0 (0..63)
    const int cc  = tid & 3;            // 16B column (0..3)

    float acc[4][4][4];
#pragma unroll
    for (int i = 0; i < 4; i++)
#pragma unroll
        for (int j = 0; j < 4; j++)
#pragma unroll
            for (int q = 0; q < 4; q++) acc[i][j][q] = 0.f;

    // ---- stage loader ----
    auto load_stage = [&](int kt, int buf) {
        const uint32_t st = sb + buf * STG;
#pragma unroll
        for (int i = 0; i < 2; i++) {
            const int row = r0c + i * 64;
            const uint32_t so = st + row * ROWB + cc * 16;
            const size_t ga = (size_t)(m0 + row) * DD + kt * BK + cc * 8;
            const size_t gb = (size_t)(n0 + row) * DD + kt * BK + cc * 8;
            CPA(so + A_HI, (const char*)(g_Xhi + ga));
            CPA(so + A_LO, (const char*)(g_Xlo + ga));
            CPA(so + B_HI, (const char*)(g_Whi + gb));
            CPA(so + B_LO, (const char*)(g_Wlo + gb));
        }
    };

    load_stage(0, 0); CP_COMMIT();
    load_stage(1, 1); CP_COMMIT();

    // per-lane ldmatrix address pieces
    const int lrow = lane & 15;
    const int lhal = (lane >> 4) << 4;  // 0 or 16 bytes (8-col half)

    for (int kt = 0; kt < NKT; kt++) {
        const int buf = kt % STAGES;
        CP_WAIT1();
        __syncthreads();
        if (kt + 2 < NKT) load_stage(kt + 2, (kt + 2) % STAGES);
        CP_COMMIT();

        const uint32_t st = sb + buf * STG;
        const uint32_t abase = st + (wm * 64 + lrow) * ROWB + lhal;
        const uint32_t bbase = st + (wn * 32 + lrow) * ROWB + lhal;

#pragma unroll
        for (int kk = 0; kk < 2; kk++) {
            uint32_t ah[4][4], al[4][4], bh[2][4], bl[2][4];
#pragma unroll
            for (int ti = 0; ti < 4; ti++) {
                LDSM4(ah[ti], abase + A_HI + ti * (16 * ROWB) + kk * 32);
                LDSM4(al[ti], abase + A_LO + ti * (16 * ROWB) + kk * 32);
            }
#pragma unroll
            for (int tj = 0; tj < 2; tj++) {
                LDSM4(bh[tj], bbase + B_HI + tj * (16 * ROWB) + kk * 32);
                LDSM4(bl[tj], bbase + B_LO + tj * (16 * ROWB) + kk * 32);
            }
#pragma unroll
            for (int ti = 0; ti < 4; ti++) {
#pragma unroll
                for (int nj = 0; nj < 4; nj++) {
                    const int tj = nj >> 1, o = nj & 1;
                    MMA(acc[ti][nj], ah[ti], bh[tj][o], bh[tj][o + 2]);
                    MMA(acc[ti][nj], ah[ti], bl[tj][o], bl[tj][o + 2]);
                    MMA(acc[ti][nj], al[ti], bh[tj][o], bh[tj][o + 2]);
                }
            }
        }
        __syncthreads();
    }

    // ---- epilogue: bias + store ----
    const int orow_base = m0 + wm * 64 + (lane >> 2);
    const int ocol_base = n0 + wn * 32 + (lane & 3) * 2;
#pragma unroll
    for (int ti = 0; ti < 4; ti++) {
        const int r0 = orow_base + ti * 16;
#pragma unroll
        for (int nj = 0; nj < 4; nj++) {
            const int c = ocol_base + nj * 8;
            const float2 bs = *reinterpret_cast<const float2*>(bias + c);
            float2 v0, v1;
            v0.x = acc[ti][nj][0] + bs.x;
            v0.y = acc[ti][nj][1] + bs.y;
            v1.x = acc[ti][nj][2] + bs.x;
            v1.y = acc[ti][nj][3] + bs.y;
            *reinterpret_cast<float2*>(Out + (size_t)r0 * ND + c) = v0;
            *reinterpret_cast<float2*>(Out + (size_t)(r0 + 8) * ND + c) = v1;
        }
    }
}

// ---------------------------------------------------------------------------
// Launch.  Inputs (metadata order): x, W_qkv, b_qkv, A_q, B_q, A_v, B_v, s0
// ---------------------------------------------------------------------------
extern "C" void kernel_launch(void* const* d_in, const int* in_sizes, int n_in,
                              void* d_out, int out_size) {
    const float* x  = (const float*)d_in[0];
    const float* W  = (const float*)d_in[1];
    const float* b  = (const float*)d_in[2];
    const float* Aq = (const float*)d_in[3];
    const float* Bq = (const float*)d_in[4];
    const float* Av = (const float*)d_in[5];
    const float* Bv = (const float*)d_in[6];
    const float* s0 = (const float*)d_in[7];
    float* out = (float*)d_out;

    conv_x<<<(MTOT * DD / 4) / 256, 256>>>((const float4*)x);
    fold_w<<<(ND * DD + 255) / 256, 256>>>(W, Aq, Bq, Av, Bv, s0);

    static bool attr_set = false;
    if (!attr_set) {
        cudaFuncSetAttribute(gemm_mma,
                             cudaFuncAttributeMaxDynamicSharedMemorySize,
                             SMEM_TOTAL);
        attr_set = true;
    }
    dim3 grid(ND / BN, MTOT / BM);      // (18, 512); x-fast => X tile L2 reuse
    gemm_mma<<<grid, 256, SMEM_TOTAL>>>(b, out);
}

// round 5
// speedup vs baseline: 3.2312x; 1.6740x over previous
#include <cuda_runtime.h>
#include <cuda_fp16.h>
#include <cstdint>

// Problem constants (B=64, S=1024, D=768, R=4)
#define DD    768
#define ND    2304
#define RR    4
#define MTOT  65536

// GEMM tiling
#define BM 128
#define BN 128
#define BK 32
#define NKT (DD / BK)        // 24
#define STAGES 3

// smem stage layout: padded rows of 40 halves (80 B) for conflict-free ldmatrix
#define ROWB   80
#define MAT_B  (128 * ROWB)  // 10240 bytes per matrix tile
#define A_HI   0
#define A_LO   (MAT_B)
#define B_W    (2 * MAT_B)
#define STG    (3 * MAT_B)   // 30720
#define SMEM_TOTAL (STAGES * STG)  // 92160

// Static device scratch (no runtime allocation allowed)
__device__ __align__(128) __half g_Xhi[(size_t)MTOT * DD];
__device__ __align__(128) __half g_Xlo[(size_t)MTOT * DD];
__device__ __align__(128) __half g_W[(size_t)ND * DD];

// ---------------------------------------------------------------------------
// PTX helpers (baseline ISA only — safe under compute_103 virtual arch)
// ---------------------------------------------------------------------------
__device__ __forceinline__ uint32_t smem_u32(const void* p) {
    uint32_t a;
    asm("{ .reg .u64 t; cvta.to.shared.u64 t, %1; cvt.u32.u64 %0, t; }"
        : "=r"(a) : "l"(p));
    return a;
}

#define CPA(saddr, gaddr) \
    asm volatile("cp.async.cg.shared.global [%0], [%1], 16;" \
                 :: "r"(saddr), "l"(gaddr))

#define CP_COMMIT() asm volatile("cp.async.commit_group;" ::: "memory")
#define CP_WAIT1()  asm volatile("cp.async.wait_group 1;" ::: "memory")

#define LDSM4(r, addr)                                                        \
    asm volatile("ldmatrix.sync.aligned.m8n8.x4.shared.b16 {%0,%1,%2,%3}, [%4];" \
                 : "=r"((r)[0]), "=r"((r)[1]), "=r"((r)[2]), "=r"((r)[3])     \
                 : "r"(addr))

#define MMA(c, a, b0, b1)                                                     \
    asm volatile("mma.sync.aligned.m16n8k16.row.col.f32.f16.f16.f32 "         \
                 "{%0,%1,%2,%3},{%4,%5,%6,%7},{%8,%9},{%0,%1,%2,%3};"         \
                 : "+f"((c)[0]), "+f"((c)[1]), "+f"((c)[2]), "+f"((c)[3])     \
                 : "r"((a)[0]), "r"((a)[1]), "r"((a)[2]), "r"((a)[3]),        \
                   "r"(b0), "r"(b1))

// ---------------------------------------------------------------------------
// Kernel 0: X fp32 -> (X_hi, X_lo) fp16 split  (22-bit effective precision)
// ---------------------------------------------------------------------------
__global__ void conv_x(const float4* __restrict__ X) {
    size_t i = (size_t)blockIdx.x * blockDim.x + threadIdx.x;   // float4 index
    float4 v = X[i];
    __half h0 = __float2half(v.x), h1 = __float2half(v.y);
    __half h2 = __float2half(v.z), h3 = __float2half(v.w);
    __half l0 = __float2half(v.x - __half2float(h0));
    __half l1 = __float2half(v.y - __half2float(h1));
    __half l2 = __float2half(v.z - __half2float(h2));
    __half l3 = __float2half(v.w - __half2float(h3));
    __half2* ph = reinterpret_cast<__half2*>(g_Xhi) + i * 2;
    __half2* pl = reinterpret_cast<__half2*>(g_Xlo) + i * 2;
    ph[0] = __half2(h0, h1);
    ph[1] = __half2(h2, h3);
    pl[0] = __half2(l0, l1);
    pl[1] = __half2(l2, l3);
}

// ---------------------------------------------------------------------------
// Kernel 1: fold LoRA into W (rank-4 update on q and v row blocks) -> fp16
// ---------------------------------------------------------------------------
__global__ void fold_w(const float* __restrict__ W,
                       const float* __restrict__ Aq, const float* __restrict__ Bq,
                       const float* __restrict__ Av, const float* __restrict__ Bv,
                       const float* __restrict__ s0p) {
    int idx = blockIdx.x * blockDim.x + threadIdx.x;
    if (idx >= ND * DD) return;
    int e = idx / DD;
    int d = idx - e * DD;
    float v = W[idx];
    float s = s0p[0];
    if (e < DD) {
        float acc = 0.f;
#pragma unroll
        for (int r = 0; r < RR; r++) acc = fmaf(Bq[e * RR + r], Aq[r * DD + d], acc);
        v = fmaf(s, acc, v);
    } else if (e >= 2 * DD) {
        int e2 = e - 2 * DD;
        float acc = 0.f;
#pragma unroll
        for (int r = 0; r < RR; r++) acc = fmaf(Bv[e2 * RR + r], Av[r * DD + d], acc);
        v = fmaf(s, acc, v);
    }
    g_W[idx] = __float2half(v);
}

// ---------------------------------------------------------------------------
// Kernel 2: fp16 mma.sync GEMM, 2-term x-split, fp32 accumulate.
//   Out[M, ND] = (Xhi + Xlo) @ W^T + bias
//   128x128x32 CTA tile, 8 warps (2x4), 64x32 warp tile, 3-stage cp.async.
//   2 CTAs/SM (92 KB smem each).
// ---------------------------------------------------------------------------
__global__ void __launch_bounds__(256, 2) gemm_mma(
    const float* __restrict__ bias, float* __restrict__ Out) {
    extern __shared__ char smem[];
    const uint32_t sb = smem_u32(smem);

    const int tid  = threadIdx.x;
    const int wid  = tid >> 5;
    const int lane = tid & 31;
    const int wm   = wid >> 2;          // 0..1  (64 rows each)
    const int wn   = wid & 3;           // 0..3  (32 cols each)
    const int n0   = blockIdx.x * BN;
    const int m0   = blockIdx.y * BM;

    // global load mapping: 512 16B chunks per matrix tile, 2 per thread
    const int r0c = tid >> 2;           // row for chunk 0 (0..63)
    const int cc  = tid & 3;            // 16B column (0..3)

    float acc[4][4][4];
#pragma unroll
    for (int i = 0; i < 4; i++)
#pragma unroll
        for (int j = 0; j < 4; j++)
#pragma unroll
            for (int q = 0; q < 4; q++) acc[i][j][q] = 0.f;

    // ---- stage loader ----
    auto load_stage = [&](int kt, int buf) {
        const uint32_t st = sb + buf * STG;
#pragma unroll
        for (int i = 0; i < 2; i++) {
            const int row = r0c + i * 64;
            const uint32_t so = st + row * ROWB + cc * 16;
            const size_t ga = (size_t)(m0 + row) * DD + kt * BK + cc * 8;
            const size_t gb = (size_t)(n0 + row) * DD + kt * BK + cc * 8;
            CPA(so + A_HI, (const char*)(g_Xhi + ga));
            CPA(so + A_LO, (const char*)(g_Xlo + ga));
            CPA(so + B_W,  (const char*)(g_W   + gb));
        }
    };

    load_stage(0, 0); CP_COMMIT();
    load_stage(1, 1); CP_COMMIT();

    // per-lane ldmatrix address pieces
    const int lrow = lane & 15;
    const int lhal = (lane >> 4) << 4;  // 0 or 16 bytes (8-col half)

    for (int kt = 0; kt < NKT; kt++) {
        const int buf = kt % STAGES;
        CP_WAIT1();
        __syncthreads();
        if (kt + 2 < NKT) load_stage(kt + 2, (kt + 2) % STAGES);
        CP_COMMIT();

        const uint32_t st = sb + buf * STG;
        const uint32_t abase = st + (wm * 64 + lrow) * ROWB + lhal;
        const uint32_t bbase = st + (wn * 32 + lrow) * ROWB + lhal;

#pragma unroll
        for (int kk = 0; kk < 2; kk++) {
            uint32_t ah[4][4], al[4][4], bw[2][4];
#pragma unroll
            for (int ti = 0; ti < 4; ti++) {
                LDSM4(ah[ti], abase + A_HI + ti * (16 * ROWB) + kk * 32);
                LDSM4(al[ti], abase + A_LO + ti * (16 * ROWB) + kk * 32);
            }
#pragma unroll
            for (int tj = 0; tj < 2; tj++)
                LDSM4(bw[tj], bbase + B_W + tj * (16 * ROWB) + kk * 32);
#pragma unroll
            for (int ti = 0; ti < 4; ti++) {
#pragma unroll
                for (int nj = 0; nj < 4; nj++) {
                    const int tj = nj >> 1, o = nj & 1;
                    MMA(acc[ti][nj], ah[ti], bw[tj][o], bw[tj][o + 2]);
                    MMA(acc[ti][nj], al[ti], bw[tj][o], bw[tj][o + 2]);
                }
            }
        }
        __syncthreads();
    }

    // ---- epilogue: bias + store ----
    const int orow_base = m0 + wm * 64 + (lane >> 2);
    const int ocol_base = n0 + wn * 32 + (lane & 3) * 2;
#pragma unroll
    for (int ti = 0; ti < 4; ti++) {
        const int r0 = orow_base + ti * 16;
#pragma unroll
        for (int nj = 0; nj < 4; nj++) {
            const int c = ocol_base + nj * 8;
            const float2 bs = *reinterpret_cast<const float2*>(bias + c);
            float2 v0, v1;
            v0.x = acc[ti][nj][0] + bs.x;
            v0.y = acc[ti][nj][1] + bs.y;
            v1.x = acc[ti][nj][2] + bs.x;
            v1.y = acc[ti][nj][3] + bs.y;
            *reinterpret_cast<float2*>(Out + (size_t)r0 * ND + c) = v0;
            *reinterpret_cast<float2*>(Out + (size_t)(r0 + 8) * ND + c) = v1;
        }
    }
}

// ---------------------------------------------------------------------------
// Launch.  Inputs (metadata order): x, W_qkv, b_qkv, A_q, B_q, A_v, B_v, s0
// ---------------------------------------------------------------------------
extern "C" void kernel_launch(void* const* d_in, const int* in_sizes, int n_in,
                              void* d_out, int out_size) {
    const float* x  = (const float*)d_in[0];
    const float* W  = (const float*)d_in[1];
    const float* b  = (const float*)d_in[2];
    const float* Aq = (const float*)d_in[3];
    const float* Bq = (const float*)d_in[4];
    const float* Av = (const float*)d_in[5];
    const float* Bv = (const float*)d_in[6];
    const float* s0 = (const float*)d_in[7];
    float* out = (float*)d_out;

    conv_x<<<(MTOT * DD / 4) / 256, 256>>>((const float4*)x);
    fold_w<<<(ND * DD + 255) / 256, 256>>>(W, Aq, Bq, Av, Bv, s0);

    static bool attr_set = false;
    if (!attr_set) {
        cudaFuncSetAttribute(gemm_mma,
                             cudaFuncAttributeMaxDynamicSharedMemorySize,
                             SMEM_TOTAL);
        attr_set = true;
    }
    dim3 grid(ND / BN, MTOT / BM);      // (18, 512); x-fast => X tile L2 reuse
    gemm_mma<<<grid, 256, SMEM_TOTAL>>>(b, out);
}

// round 6
// speedup vs baseline: 5.8646x; 1.8150x over previous
#include <cuda_runtime.h>
#include <cuda_fp16.h>
#include <cstdint>

// Problem constants (B=64, S=1024, D=768, R=4)
#define DD    768
#define ND    2304
#define RR    4
#define MTOT  65536

// GEMM tiling
#define BM 128
#define BN 128
#define BK 32
#define NKT (DD / BK)        // 24
#define STAGES 4

// smem stage layout: padded rows of 40 halves (80 B) for conflict-free ldmatrix
#define ROWB   80
#define MAT_B  (128 * ROWB)  // 10240 bytes per matrix tile
#define A_T    0
#define B_T    (MAT_B)
#define STG    (2 * MAT_B)   // 20480
#define SMEM_TOTAL (STAGES * STG)  // 81920

// Static device scratch (no runtime allocation allowed)
__device__ __align__(128) __half g_X[(size_t)MTOT * DD];
__device__ __align__(128) __half g_W[(size_t)ND * DD];

// ---------------------------------------------------------------------------
// PTX helpers (baseline ISA only — safe under compute_103 virtual arch)
// ---------------------------------------------------------------------------
__device__ __forceinline__ uint32_t smem_u32(const void* p) {
    uint32_t a;
    asm("{ .reg .u64 t; cvta.to.shared.u64 t, %1; cvt.u32.u64 %0, t; }"
        : "=r"(a) : "l"(p));
    return a;
}

#define CPA(saddr, gaddr) \
    asm volatile("cp.async.cg.shared.global [%0], [%1], 16;" \
                 :: "r"(saddr), "l"(gaddr))

#define CP_COMMIT() asm volatile("cp.async.commit_group;" ::: "memory")
#define CP_WAIT2()  asm volatile("cp.async.wait_group 2;" ::: "memory")

#define LDSM4(r, addr)                                                        \
    asm volatile("ldmatrix.sync.aligned.m8n8.x4.shared.b16 {%0,%1,%2,%3}, [%4];" \
                 : "=r"((r)[0]), "=r"((r)[1]), "=r"((r)[2]), "=r"((r)[3])     \
                 : "r"(addr))

#define MMA(c, a, b0, b1)                                                     \
    asm volatile("mma.sync.aligned.m16n8k16.row.col.f32.f16.f16.f32 "         \
                 "{%0,%1,%2,%3},{%4,%5,%6,%7},{%8,%9},{%0,%1,%2,%3};"         \
                 : "+f"((c)[0]), "+f"((c)[1]), "+f"((c)[2]), "+f"((c)[3])     \
                 : "r"((a)[0]), "r"((a)[1]), "r"((a)[2]), "r"((a)[3]),        \
                   "r"(b0), "r"(b1))

// ---------------------------------------------------------------------------
// Kernel 0: X fp32 -> fp16
// ---------------------------------------------------------------------------
__global__ void conv_x(const float4* __restrict__ X) {
    size_t i = (size_t)blockIdx.x * blockDim.x + threadIdx.x;   // float4 index
    float4 v = X[i];
    __half2* ph = reinterpret_cast<__half2*>(g_X) + i * 2;
    ph[0] = __floats2half2_rn(v.x, v.y);
    ph[1] = __floats2half2_rn(v.z, v.w);
}

// ---------------------------------------------------------------------------
// Kernel 1: fold LoRA into W (rank-4 update on q and v row blocks) -> fp16
// ---------------------------------------------------------------------------
__global__ void fold_w(const float* __restrict__ W,
                       const float* __restrict__ Aq, const float* __restrict__ Bq,
                       const float* __restrict__ Av, const float* __restrict__ Bv,
                       const float* __restrict__ s0p) {
    int idx = blockIdx.x * blockDim.x + threadIdx.x;
    if (idx >= ND * DD) return;
    int e = idx / DD;
    int d = idx - e * DD;
    float v = W[idx];
    float s = s0p[0];
    if (e < DD) {
        float acc = 0.f;
#pragma unroll
        for (int r = 0; r < RR; r++) acc = fmaf(Bq[e * RR + r], Aq[r * DD + d], acc);
        v = fmaf(s, acc, v);
    } else if (e >= 2 * DD) {
        int e2 = e - 2 * DD;
        float acc = 0.f;
#pragma unroll
        for (int r = 0; r < RR; r++) acc = fmaf(Bv[e2 * RR + r], Av[r * DD + d], acc);
        v = fmaf(s, acc, v);
    }
    g_W[idx] = __float2half(v);
}

// ---------------------------------------------------------------------------
// Kernel 2: fp16 mma.sync GEMM, single term, fp32 accumulate.
//   Out[M, ND] = X @ W^T + bias
//   128x128x32 CTA tile, 8 warps (2x4), 64x32 warp tile, 4-stage cp.async.
//   2 CTAs/SM (80 KB smem each).
// ---------------------------------------------------------------------------
__global__ void __launch_bounds__(256, 2) gemm_mma(
    const float* __restrict__ bias, float* __restrict__ Out) {
    extern __shared__ char smem[];
    const uint32_t sb = smem_u32(smem);

    const int tid  = threadIdx.x;
    const int wid  = tid >> 5;
    const int lane = tid & 31;
    const int wm   = wid >> 2;          // 0..1  (64 rows each)
    const int wn   = wid & 3;           // 0..3  (32 cols each)
    const int n0   = blockIdx.x * BN;
    const int m0   = blockIdx.y * BM;

    // global load mapping: 512 16B chunks per matrix tile, 2 per thread
    const int r0c = tid >> 2;           // row for chunk 0 (0..63)
    const int cc  = tid & 3;            // 16B column (0..3)

    float acc[4][4][4];
#pragma unroll
    for (int i = 0; i < 4; i++)
#pragma unroll
        for (int j = 0; j < 4; j++)
#pragma unroll
            for (int q = 0; q < 4; q++) acc[i][j][q] = 0.f;

    // ---- stage loader ----
    auto load_stage = [&](int kt, int buf) {
        const uint32_t st = sb + buf * STG;
#pragma unroll
        for (int i = 0; i < 2; i++) {
            const int row = r0c + i * 64;
            const uint32_t so = st + row * ROWB + cc * 16;
            const size_t ga = (size_t)(m0 + row) * DD + kt * BK + cc * 8;
            const size_t gb = (size_t)(n0 + row) * DD + kt * BK + cc * 8;
            CPA(so + A_T, (const char*)(g_X + ga));
            CPA(so + B_T, (const char*)(g_W + gb));
        }
    };

    load_stage(0, 0); CP_COMMIT();
    load_stage(1, 1); CP_COMMIT();
    load_stage(2, 2); CP_COMMIT();

    // per-lane ldmatrix address pieces
    const int lrow = lane & 15;
    const int lhal = (lane >> 4) << 4;  // 0 or 16 bytes (8-col half)

    for (int kt = 0; kt < NKT; kt++) {
        const int buf = kt % STAGES;
        CP_WAIT2();
        __syncthreads();
        if (kt + 3 < NKT) load_stage(kt + 3, (kt + 3) % STAGES);
        CP_COMMIT();

        const uint32_t st = sb + buf * STG;
        const uint32_t abase = st + (wm * 64 + lrow) * ROWB + lhal;
        const uint32_t bbase = st + (wn * 32 + lrow) * ROWB + lhal;

#pragma unroll
        for (int kk = 0; kk < 2; kk++) {
            uint32_t aw[4][4], bw[2][4];
#pragma unroll
            for (int ti = 0; ti < 4; ti++)
                LDSM4(aw[ti], abase + A_T + ti * (16 * ROWB) + kk * 32);
#pragma unroll
            for (int tj = 0; tj < 2; tj++)
                LDSM4(bw[tj], bbase + B_T + tj * (16 * ROWB) + kk * 32);
#pragma unroll
            for (int ti = 0; ti < 4; ti++) {
#pragma unroll
                for (int nj = 0; nj < 4; nj++) {
                    const int tj = nj >> 1, o = nj & 1;
                    MMA(acc[ti][nj], aw[ti], bw[tj][o], bw[tj][o + 2]);
                }
            }
        }
        __syncthreads();
    }

    // ---- epilogue: bias + store ----
    const int orow_base = m0 + wm * 64 + (lane >> 2);
    const int ocol_base = n0 + wn * 32 + (lane & 3) * 2;
#pragma unroll
    for (int ti = 0; ti < 4; ti++) {
        const int r0 = orow_base + ti * 16;
#pragma unroll
        for (int nj = 0; nj < 4; nj++) {
            const int c = ocol_base + nj * 8;
            const float2 bs = *reinterpret_cast<const float2*>(bias + c);
            float2 v0, v1;
            v0.x = acc[ti][nj][0] + bs.x;
            v0.y = acc[ti][nj][1] + bs.y;
            v1.x = acc[ti][nj][2] + bs.x;
            v1.y = acc[ti][nj][3] + bs.y;
            *reinterpret_cast<float2*>(Out + (size_t)r0 * ND + c) = v0;
            *reinterpret_cast<float2*>(Out + (size_t)(r0 + 8) * ND + c) = v1;
        }
    }
}

// ---------------------------------------------------------------------------
// Launch.  Inputs (metadata order): x, W_qkv, b_qkv, A_q, B_q, A_v, B_v, s0
// ---------------------------------------------------------------------------
extern "C" void kernel_launch(void* const* d_in, const int* in_sizes, int n_in,
                              void* d_out, int out_size) {
    const float* x  = (const float*)d_in[0];
    const float* W  = (const float*)d_in[1];
    const float* b  = (const float*)d_in[2];
    const float* Aq = (const float*)d_in[3];
    const float* Bq = (const float*)d_in[4];
    const float* Av = (const float*)d_in[5];
    const float* Bv = (const float*)d_in[6];
    const float* s0 = (const float*)d_in[7];
    float* out = (float*)d_out;

    conv_x<<<(MTOT * DD / 4) / 256, 256>>>((const float4*)x);
    fold_w<<<(ND * DD + 255) / 256, 256>>>(W, Aq, Bq, Av, Bv, s0);

    static bool attr_set = false;
    if (!attr_set) {
        cudaFuncSetAttribute(gemm_mma,
                             cudaFuncAttributeMaxDynamicSharedMemorySize,
                             SMEM_TOTAL);
        attr_set = true;
    }
    dim3 grid(ND / BN, MTOT / BM);      // (18, 512); x-fast => X tile L2 reuse
    gemm_mma<<<grid, 256, SMEM_TOTAL>>>(b, out);
}